// round 16
// baseline (speedup 1.0000x reference)
#include <cuda_runtime.h>
#include <cuda_fp16.h>
#include <cstdint>
#include <cstdio>

// ---------------- problem constants ----------------
#define NP 100000
#define NS 50000
#define PD 1024
#define SD 512
#define HF 64
#define EPN 3200000
#define ESN 1600000
#define ELN 2000000

// ---------------- device scratch (static; zero-initialized at load) ----------------
// feature buffers hold fp16 rows (64 halfs = 128B)
__device__ float g_bufP0[(size_t)NP * HF / 2];
__device__ float g_bufP1[(size_t)NP * HF / 2];
__device__ float g_bufS0[(size_t)NS * HF / 2];
__device__ float g_bufS1[(size_t)NS * HF / 2];
__device__ float g_dinvP[NP];
__device__ float g_dinvS[NS];
__device__ int   g_rowP[NP + 1];
__device__ int   g_rowS[NS + 1];
__device__ int   g_curP[NP];   // counts -> cursor; zero at start of each replay
__device__ int   g_curS[NS];
__device__ int2  g_srcwP[EPN]; // (src index, dinv[src] as float bits)
__device__ int2  g_srcwS[ESN];
__device__ float g_Wc[128 * 64 + 64];      // Wcomb [128,64] row-major, then bcomb[64]
__device__ float g_W2[2 * (64 * 64 + 64)]; // W2cP[64x64], b2cP[64], W2cS[64x64], b2cS[64]
__device__ int   g_bsum[256];

// ================= CSR build (both graphs in shared kernels) =================
__global__ void k_countB(const int* __restrict__ eiP, int EP,
                         const int* __restrict__ eiS, int ES,
                         int* __restrict__ cntP, int* __restrict__ cntS) {
    int e = blockIdx.x * blockDim.x + threadIdx.x;
    if (e < EP) {
        atomicAdd(&cntP[eiP[EP + e]], 1);
    } else if (e < EP + ES) {
        int l = e - EP;
        atomicAdd(&cntS[eiS[ES + l]], 1);
    }
}

__global__ void k_scan1B(const int* __restrict__ cntP, const int* __restrict__ cntS,
                         int* __restrict__ rowP, int* __restrict__ rowS,
                         int* __restrict__ blockSums, int nbP) {
    __shared__ int sh[1024];
    int b = blockIdx.x;
    const int* cnt;
    int* rowOut;
    int N, local0;
    if (b < nbP) { cnt = cntP; rowOut = rowP; N = NP; local0 = b * 1024; }
    else         { cnt = cntS; rowOut = rowS; N = NS; local0 = (b - nbP) * 1024; }
    int i = local0 + threadIdx.x;
    int v = (i < N) ? cnt[i] : 0;
    sh[threadIdx.x] = v;
    __syncthreads();
    for (int off = 1; off < 1024; off <<= 1) {
        int t = 0;
        if ((int)threadIdx.x >= off) t = sh[threadIdx.x - off];
        __syncthreads();
        sh[threadIdx.x] += t;
        __syncthreads();
    }
    int incl = sh[threadIdx.x];
    if (i < N) rowOut[i] = incl - v;
    if (threadIdx.x == 1023) blockSums[b] = incl;
}

__global__ void k_scan2B(int* __restrict__ blockSums, int nbP, int nbS) {
    __shared__ int sh[1024];
    int nb = nbP + nbS;
    int t = threadIdx.x;
    int v = (t < nb) ? blockSums[t] : 0;
    sh[t] = v;
    __syncthreads();
    for (int off = 1; off < 1024; off <<= 1) {
        int x = 0;
        if (t >= off) x = sh[t - off];
        __syncthreads();
        sh[t] += x;
        __syncthreads();
    }
    int excl = sh[t] - v;
    int sumP = sh[nbP - 1];
    if (t < nbP) blockSums[t] = excl;
    else if (t < nb) blockSums[t] = excl - sumP;
}

__global__ void k_scan3B(int* __restrict__ rowP, int* __restrict__ rowS,
                         int* __restrict__ curP, int* __restrict__ curS,
                         const int* __restrict__ blockSums, int nbP,
                         int EP, int ES,
                         float* __restrict__ dinvP, float* __restrict__ dinvS) {
    int i = blockIdx.x * blockDim.x + threadIdx.x;
    if (i < NP) {
        int r = rowP[i] + blockSums[i >> 10];
        int deg = curP[i];
        rowP[i] = r;
        curP[i] = r;
        dinvP[i] = rsqrtf((float)(deg + 1));
        if (i == 0) rowP[NP] = EP;
    } else if (i < NP + NS) {
        int l = i - NP;
        int r = rowS[l] + blockSums[(l >> 10) + nbP];
        int deg = curS[l];
        rowS[l] = r;
        curS[l] = r;
        dinvS[l] = rsqrtf((float)(deg + 1));
        if (l == 0) rowS[NS] = ES;
    }
}

// fill stores (src, dinv[src]) pairs — dinv is ready (scan3B precedes fillB)
__global__ void k_fillB(const int* __restrict__ eiP, int EP,
                        const int* __restrict__ eiS, int ES,
                        int* __restrict__ curP, int* __restrict__ curS,
                        int2* __restrict__ srcwP, int2* __restrict__ srcwS,
                        const float* __restrict__ dinvP, const float* __restrict__ dinvS) {
    int e = blockIdx.x * blockDim.x + threadIdx.x;
    if (e < EP) {
        int d = eiP[EP + e];
        int src = eiP[e];
        int p = atomicAdd(&curP[d], 1);
        srcwP[p] = make_int2(src, __float_as_int(dinvP[src]));
    } else if (e < EP + ES) {
        int l = e - EP;
        int d = eiS[ES + l];
        int src = eiS[l];
        int p = atomicAdd(&curS[d], 1);
        srcwS[p] = make_int2(src, __float_as_int(dinvS[src]));
    }
}

__global__ void k_reset(int* __restrict__ curP, int* __restrict__ curS) {
    int i = blockIdx.x * blockDim.x + threadIdx.x;
    if (i < NP) curP[i] = 0;
    if (i < NS) curS[i] = 0;
}

// ======== tf32 tensor-core GEMM bodies (round-6 proven tiling) ========
#define BM 128
#define BN 64
#define BK 32
#define XPAD 40
#define WPAD 72

__device__ __forceinline__ unsigned f2tf32(float f) {
    unsigned u;
    asm("cvt.rna.tf32.f32 %0, %1;" : "=r"(u) : "f"(f));
    return u;
}

__device__ __forceinline__ void mma_tile(const unsigned* Xs, const unsigned* Ws,
                                         int rb, int cb, int lq, int lr,
                                         float acc[2][4][4]) {
#pragma unroll
    for (int ks = 0; ks < 4; ks++) {
        int k0 = ks * 8;
        unsigned a[2][4];
#pragma unroll
        for (int mt = 0; mt < 2; mt++) {
            int r = rb + mt * 16 + lq;
            a[mt][0] = Xs[r * XPAD + k0 + lr];
            a[mt][1] = Xs[(r + 8) * XPAD + k0 + lr];
            a[mt][2] = Xs[r * XPAD + k0 + 4 + lr];
            a[mt][3] = Xs[(r + 8) * XPAD + k0 + 4 + lr];
        }
        unsigned b[4][2];
#pragma unroll
        for (int nb = 0; nb < 4; nb++) {
            int c = cb + nb * 8 + lq;
            b[nb][0] = Ws[(k0 + lr) * WPAD + c];
            b[nb][1] = Ws[(k0 + 4 + lr) * WPAD + c];
        }
#pragma unroll
        for (int mt = 0; mt < 2; mt++)
#pragma unroll
            for (int nb = 0; nb < 4; nb++)
                asm volatile(
                    "mma.sync.aligned.m16n8k8.row.col.f32.tf32.tf32.f32 "
                    "{%0,%1,%2,%3}, {%4,%5,%6,%7}, {%8,%9}, {%0,%1,%2,%3};"
                    : "+f"(acc[mt][nb][0]), "+f"(acc[mt][nb][1]),
                      "+f"(acc[mt][nb][2]), "+f"(acc[mt][nb][3])
                    : "r"(a[mt][0]), "r"(a[mt][1]), "r"(a[mt][2]), "r"(a[mt][3]),
                      "r"(b[nb][0]), "r"(b[nb][1]));
    }
}

__device__ __forceinline__ void epilogue_h(__half* Y, int M, int row0, int rb, int cb,
                                           int lq, int lr, float acc[2][4][4]) {
#pragma unroll
    for (int mt = 0; mt < 2; mt++) {
#pragma unroll
        for (int nb = 0; nb < 4; nb++) {
            int r = row0 + rb + mt * 16 + lq;
            int c = cb + nb * 8 + 2 * lr;
            if (r < M)
                ((__half2*)Y)[(size_t)r * 32 + (c >> 1)] =
                    __floats2half2_rn(acc[mt][nb][0], acc[mt][nb][1]);
            if (r + 8 < M)
                ((__half2*)Y)[(size_t)(r + 8) * 32 + (c >> 1)] =
                    __floats2half2_rn(acc[mt][nb][2], acc[mt][nb][3]);
        }
    }
}

// fp32 X -> fp16 Y (layer 1)
__device__ __forceinline__ void gemm_body(const float* __restrict__ X,
                                          const float* __restrict__ W,
                                          __half* __restrict__ Y, int M, int K,
                                          int row0, unsigned* Xs, unsigned* Ws) {
    int tid = threadIdx.x;
    int wid = tid >> 5, lane = tid & 31;
    int lq = lane >> 2, lr = lane & 3;
    int rb = (wid & 3) * 32, cb = (wid >> 2) * 32;
    int nt = K / BK;

    int xr[4], xc[4];
#pragma unroll
    for (int l = 0; l < 4; l++) {
        int idx = tid + l * 256;
        xr[l] = idx >> 3;
        xc[l] = idx & 7;
    }
    int wk[2], wc[2];
#pragma unroll
    for (int l = 0; l < 2; l++) {
        int idx = tid + l * 256;
        wk[l] = idx >> 4;
        wc[l] = idx & 15;
    }

    float acc[2][4][4];
#pragma unroll
    for (int mt = 0; mt < 2; mt++)
#pragma unroll
        for (int nb = 0; nb < 4; nb++)
#pragma unroll
            for (int j = 0; j < 4; j++) acc[mt][nb][j] = 0.f;

    float4 xv[4], wv[2];
#pragma unroll
    for (int l = 0; l < 4; l++) {
        int gr = row0 + xr[l];
        xv[l] = (gr < M) ? *(const float4*)(X + (size_t)gr * K + xc[l] * 4)
                         : make_float4(0.f, 0.f, 0.f, 0.f);
    }
#pragma unroll
    for (int l = 0; l < 2; l++)
        wv[l] = *(const float4*)(W + (size_t)wk[l] * HF + wc[l] * 4);
#pragma unroll
    for (int l = 0; l < 4; l++) {
        uint4 u = make_uint4(f2tf32(xv[l].x), f2tf32(xv[l].y), f2tf32(xv[l].z), f2tf32(xv[l].w));
        *(uint4*)&Xs[xr[l] * XPAD + xc[l] * 4] = u;
    }
#pragma unroll
    for (int l = 0; l < 2; l++) {
        uint4 u = make_uint4(f2tf32(wv[l].x), f2tf32(wv[l].y), f2tf32(wv[l].z), f2tf32(wv[l].w));
        *(uint4*)&Ws[wk[l] * WPAD + wc[l] * 4] = u;
    }
    __syncthreads();

    for (int t = 0; t < nt; t++) {
        if (t + 1 < nt) {
            const float* Xn = X + (size_t)(t + 1) * BK;
            const float* Wn = W + (size_t)(t + 1) * BK * HF;
#pragma unroll
            for (int l = 0; l < 4; l++) {
                int gr = row0 + xr[l];
                xv[l] = (gr < M) ? *(const float4*)(Xn + (size_t)gr * K + xc[l] * 4)
                                 : make_float4(0.f, 0.f, 0.f, 0.f);
            }
#pragma unroll
            for (int l = 0; l < 2; l++)
                wv[l] = *(const float4*)(Wn + (size_t)wk[l] * HF + wc[l] * 4);
        }
        mma_tile(Xs, Ws, rb, cb, lq, lr, acc);
        __syncthreads();
        if (t + 1 < nt) {
#pragma unroll
            for (int l = 0; l < 4; l++) {
                uint4 u = make_uint4(f2tf32(xv[l].x), f2tf32(xv[l].y), f2tf32(xv[l].z), f2tf32(xv[l].w));
                *(uint4*)&Xs[xr[l] * XPAD + xc[l] * 4] = u;
            }
#pragma unroll
            for (int l = 0; l < 2; l++) {
                uint4 u = make_uint4(f2tf32(wv[l].x), f2tf32(wv[l].y), f2tf32(wv[l].z), f2tf32(wv[l].w));
                *(uint4*)&Ws[wk[l] * WPAD + wc[l] * 4] = u;
            }
            __syncthreads();
        }
    }
    epilogue_h(Y, M, row0, rb, cb, lq, lr, acc);
}

// fp16 X -> fp16 Y (layer 2, K=64)
__device__ __forceinline__ void gemm_body_h(const __half* __restrict__ X,
                                            const float* __restrict__ W,
                                            __half* __restrict__ Y, int M, int K,
                                            int row0, unsigned* Xs, unsigned* Ws) {
    int tid = threadIdx.x;
    int wid = tid >> 5, lane = tid & 31;
    int lq = lane >> 2, lr = lane & 3;
    int rb = (wid & 3) * 32, cb = (wid >> 2) * 32;
    int nt = K / BK;

    int xr[2], xc[2];
#pragma unroll
    for (int l = 0; l < 2; l++) {
        int idx = tid + l * 256;
        xr[l] = idx >> 2;
        xc[l] = idx & 3;
    }
    int wk[2], wc[2];
#pragma unroll
    for (int l = 0; l < 2; l++) {
        int idx = tid + l * 256;
        wk[l] = idx >> 4;
        wc[l] = idx & 15;
    }

    float acc[2][4][4];
#pragma unroll
    for (int mt = 0; mt < 2; mt++)
#pragma unroll
        for (int nb = 0; nb < 4; nb++)
#pragma unroll
            for (int j = 0; j < 4; j++) acc[mt][nb][j] = 0.f;

    for (int t = 0; t < nt; t++) {
#pragma unroll
        for (int l = 0; l < 2; l++) {
            int gr = row0 + xr[l];
            uint4 v = make_uint4(0u, 0u, 0u, 0u);
            if (gr < M)
                v = *(const uint4*)(X + (size_t)gr * K + t * BK + xc[l] * 8);
            const __half2* hp = (const __half2*)&v;
            unsigned o[8];
#pragma unroll
            for (int j = 0; j < 4; j++) {
                float2 f = __half22float2(hp[j]);
                o[2 * j] = f2tf32(f.x);
                o[2 * j + 1] = f2tf32(f.y);
            }
            *(uint4*)&Xs[xr[l] * XPAD + xc[l] * 8]     = make_uint4(o[0], o[1], o[2], o[3]);
            *(uint4*)&Xs[xr[l] * XPAD + xc[l] * 8 + 4] = make_uint4(o[4], o[5], o[6], o[7]);
        }
#pragma unroll
        for (int l = 0; l < 2; l++) {
            float4 w = *(const float4*)(W + (size_t)(t * BK + wk[l]) * HF + wc[l] * 4);
            uint4 u = make_uint4(f2tf32(w.x), f2tf32(w.y), f2tf32(w.z), f2tf32(w.w));
            *(uint4*)&Ws[wk[l] * WPAD + wc[l] * 4] = u;
        }
        __syncthreads();
        mma_tile(Xs, Ws, rb, cb, lq, lr, acc);
        __syncthreads();
    }
    epilogue_h(Y, M, row0, rb, cb, lq, lr, acc);
}

__global__ __launch_bounds__(256, 2) void k_gemm2(
    const float* __restrict__ X0, const float* __restrict__ W0, __half* __restrict__ Y0,
    int M0, int K0, int nb0,
    const float* __restrict__ X1, const float* __restrict__ W1, __half* __restrict__ Y1,
    int M1, int K1) {
    __shared__ unsigned Xs[BM * XPAD];
    __shared__ unsigned Ws[BK * WPAD];
    int b = blockIdx.x;
    if (b < nb0) gemm_body(X0, W0, Y0, M0, K0, b * BM, Xs, Ws);
    else         gemm_body(X1, W1, Y1, M1, K1, (b - nb0) * BM, Xs, Ws);
}

__global__ __launch_bounds__(256, 2) void k_gemm2h(
    const __half* __restrict__ X0, const float* __restrict__ W0, __half* __restrict__ Y0,
    int M0, int nb0,
    const __half* __restrict__ X1, const float* __restrict__ W1, __half* __restrict__ Y1,
    int M1) {
    __shared__ unsigned Xs[BM * XPAD];
    __shared__ unsigned Ws[BK * WPAD];
    int b = blockIdx.x;
    if (b < nb0) gemm_body_h(X0, W0, Y0, M0, HF, b * BM, Xs, Ws);
    else         gemm_body_h(X1, W1, Y1, M1, HF, (b - nb0) * BM, Xs, Ws);
}

// ---------------- merged GCN aggregation (fp16 features; (src,w) pairs) ----------------
__device__ __forceinline__ void agg_node(const __half* __restrict__ H, __half* __restrict__ OUT,
                                         const int* __restrict__ row, const int2* __restrict__ srcw,
                                         const float* __restrict__ dinv, const float* __restrict__ bias,
                                         int dst, int lane) {
    int half = lane >> 4;     // 0: even edges, 1: odd edges
    int hl = lane & 15;       // uint2 index within 128B row
    const uint2* Hp = (const uint2*)H;
    float4 a0 = make_float4(0.f, 0.f, 0.f, 0.f);
    float4 a1 = make_float4(0.f, 0.f, 0.f, 0.f);
    int s = row[dst], e = row[dst + 1];
    int i = s;
    for (; i + 4 <= e; i += 4) {
        int2 sw0 = srcw[i + half];
        int2 sw1 = srcw[i + 2 + half];
        float d0 = __int_as_float(sw0.y);
        float d1 = __int_as_float(sw1.y);
        uint2 u0 = Hp[(size_t)sw0.x * 16 + hl];
        uint2 u1 = Hp[(size_t)sw1.x * 16 + hl];
        float2 f00 = __half22float2(*(__half2*)&u0.x);
        float2 f01 = __half22float2(*(__half2*)&u0.y);
        float2 f10 = __half22float2(*(__half2*)&u1.x);
        float2 f11 = __half22float2(*(__half2*)&u1.y);
        a0.x += f00.x * d0; a0.y += f00.y * d0; a0.z += f01.x * d0; a0.w += f01.y * d0;
        a1.x += f10.x * d1; a1.y += f10.y * d1; a1.z += f11.x * d1; a1.w += f11.y * d1;
    }
    for (; i < e; i += 2) {
        int idx = i + half;
        if (idx < e) {
            int2 sw = srcw[idx];
            float d = __int_as_float(sw.y);
            uint2 u = Hp[(size_t)sw.x * 16 + hl];
            float2 f0 = __half22float2(*(__half2*)&u.x);
            float2 f1 = __half22float2(*(__half2*)&u.y);
            a0.x += f0.x * d; a0.y += f0.y * d; a0.z += f1.x * d; a0.w += f1.y * d;
        }
    }
    float4 acc = make_float4(a0.x + a1.x, a0.y + a1.y, a0.z + a1.z, a0.w + a1.w);
    acc.x += __shfl_down_sync(0xffffffffu, acc.x, 16);
    acc.y += __shfl_down_sync(0xffffffffu, acc.y, 16);
    acc.z += __shfl_down_sync(0xffffffffu, acc.z, 16);
    acc.w += __shfl_down_sync(0xffffffffu, acc.w, 16);
    if (half == 0) {
        float di = dinv[dst];
        uint2 us = Hp[(size_t)dst * 16 + hl];   // self-loop term
        float2 s0 = __half22float2(*(__half2*)&us.x);
        float2 s1 = __half22float2(*(__half2*)&us.y);
        float4 b4 = ((const float4*)bias)[hl];
        float4 o;
        o.x = (acc.x + s0.x * di) * di + b4.x;
        o.y = (acc.y + s0.y * di) * di + b4.y;
        o.z = (acc.z + s1.x * di) * di + b4.z;
        o.w = (acc.w + s1.y * di) * di + b4.w;
        __half2 p0 = __floats2half2_rn(o.x, o.y);
        __half2 p1 = __floats2half2_rn(o.z, o.w);
        uint2 u;
        u.x = *(unsigned*)&p0;
        u.y = *(unsigned*)&p1;
        ((uint2*)OUT)[(size_t)dst * 16 + hl] = u;
    }
}

__global__ void k_aggregate2(const __half* __restrict__ HP, __half* __restrict__ OP,
                             const int* __restrict__ rowP, const int2* __restrict__ srcwP,
                             const float* __restrict__ dinvP, const float* __restrict__ biasP,
                             const __half* __restrict__ HS, __half* __restrict__ OS,
                             const int* __restrict__ rowS, const int2* __restrict__ srcwS,
                             const float* __restrict__ dinvS, const float* __restrict__ biasS) {
    int warp = (blockIdx.x * blockDim.x + threadIdx.x) >> 5;
    int lane = threadIdx.x & 31;
    if (warp < NP) {
        agg_node(HP, OP, rowP, srcwP, dinvP, biasP, warp, lane);
    } else if (warp < NP + NS) {
        agg_node(HS, OS, rowS, srcwS, dinvS, biasS, warp - NP, lane);
    }
}

// ---- fused prep: Wc = Wproj@Wl1 (+bcomb), then W2cP/W2cS = Wp2/Ws2 @ Wc halves ----
__global__ void k_prep(const float* __restrict__ Wproj, const float* __restrict__ bproj,
                       const float* __restrict__ Wl1, const float* __restrict__ bl1,
                       const float* __restrict__ Wp2, const float* __restrict__ bp2,
                       const float* __restrict__ Ws2, const float* __restrict__ bs2,
                       float* __restrict__ Wc, float* __restrict__ W2) {
    extern __shared__ float sh[];
    float* sWl1 = sh;
    float* sWc  = sh + 128 * 64;
    for (int i = threadIdx.x; i < 128 * 64; i += blockDim.x) sWl1[i] = Wl1[i];
    __syncthreads();
    for (int o = threadIdx.x; o < 128 * 64; o += blockDim.x) {
        int i = o >> 6, j = o & 63;
        float s = 0.f;
        for (int k = 0; k < 128; k++) s += Wproj[i * 128 + k] * sWl1[k * 64 + j];
        sWc[o] = s;
        Wc[o] = s;
    }
    for (int j = threadIdx.x; j < 64; j += blockDim.x) {
        float s = bl1[j];
        for (int k = 0; k < 128; k++) s += bproj[k] * sWl1[k * 64 + j];
        Wc[128 * 64 + j] = s;
    }
    __syncthreads();
    float* W2cP = W2;
    float* b2cP = W2 + 64 * 64;
    float* W2cS = W2 + 64 * 64 + 64;
    float* b2cS = W2 + 2 * 64 * 64 + 64;
    for (int o = threadIdx.x; o < 64 * 64; o += blockDim.x) {
        int i = o >> 6, j = o & 63;
        float sp = 0.f, ss = 0.f;
        for (int k = 0; k < 64; k++) {
            sp += Wp2[i * 64 + k] * sWc[k * 64 + j];
            ss += Ws2[i * 64 + k] * sWc[(64 + k) * 64 + j];
        }
        W2cP[o] = sp;
        W2cS[o] = ss;
    }
    for (int j = threadIdx.x; j < 64; j += blockDim.x) {
        float sp = 0.f, ss = 0.f;
        for (int k = 0; k < 64; k++) {
            sp += bp2[k] * sWc[k * 64 + j];
            ss += bs2[k] * sWc[(64 + k) * 64 + j];
        }
        b2cP[j] = sp;
        b2cS[j] = ss;
    }
}
#define PREP_SMEM (2 * 128 * 64 * 4)   // 64 KB

// ---------------- link predictor: fp16 features, 2 edges per warp ----------------
__global__ void k_link(const __half* __restrict__ Ap, const __half* __restrict__ As,
                       const int* __restrict__ ep, const int* __restrict__ es,
                       const float* __restrict__ bc, const float* __restrict__ wl2,
                       const float* __restrict__ bl2, float* __restrict__ out, int EL) {
    int warp = (blockIdx.x * blockDim.x + threadIdx.x) >> 5;
    int lane = threadIdx.x & 31;
    int half = lane >> 4;
    int hl = lane & 15;
    int e = 2 * warp + half;
    if (e >= EL) return;
    int p = ep[e];
    int s = es[e];
    uint2 ua = ((const uint2*)Ap)[(size_t)p * 16 + hl];
    uint2 ub = ((const uint2*)As)[(size_t)s * 16 + hl];
    float2 a0 = __half22float2(*(__half2*)&ua.x);
    float2 a1 = __half22float2(*(__half2*)&ua.y);
    float2 b0 = __half22float2(*(__half2*)&ub.x);
    float2 b1 = __half22float2(*(__half2*)&ub.y);
    float4 c = ((const float4*)bc)[hl];
    float4 w = ((const float4*)wl2)[hl];
    float h0 = fmaxf(a0.x + b0.x + c.x, 0.f);
    float h1 = fmaxf(a0.y + b0.y + c.y, 0.f);
    float h2 = fmaxf(a1.x + b1.x + c.z, 0.f);
    float h3 = fmaxf(a1.y + b1.y + c.w, 0.f);
    float part = h0 * w.x + h1 * w.y + h2 * w.z + h3 * w.w;
#pragma unroll
    for (int off = 8; off; off >>= 1) part += __shfl_down_sync(0xffffffffu, part, off, 16);
    if (hl == 0) out[e] = part + bl2[0];
}

// ---------------- host orchestration ----------------
static inline int cdiv(int a, int b) { return (a + b - 1) / b; }

// streams/events created ONCE (pre-baseline on the correctness call) and reused.
static cudaStream_t g_s1 = nullptr, g_s2 = nullptr;
static cudaEvent_t g_evRoot, g_evCSR, g_evPrep, g_evTail;

extern "C" void kernel_launch(void* const* d_in, const int* in_sizes, int n_in,
                              void* d_out, int out_size) {
    const float* x_p  = (const float*)d_in[0];
    const float* x_s  = (const float*)d_in[1];
    const int*   ei_p = (const int*)d_in[2];
    const int*   ei_s = (const int*)d_in[3];
    const int*   ed_p = (const int*)d_in[4];
    const int*   ed_s = (const int*)d_in[5];
    const float* Wp1 = (const float*)d_in[6];
    const float* bp1 = (const float*)d_in[7];
    const float* Ws1 = (const float*)d_in[8];
    const float* bs1 = (const float*)d_in[9];
    const float* Wp2 = (const float*)d_in[10];
    const float* bp2 = (const float*)d_in[11];
    const float* Ws2 = (const float*)d_in[12];
    const float* bs2 = (const float*)d_in[13];
    const float* Wproj = (const float*)d_in[14];
    const float* bproj = (const float*)d_in[15];
    const float* Wl1 = (const float*)d_in[16];
    const float* bl1 = (const float*)d_in[17];
    const float* Wl2 = (const float*)d_in[18];
    const float* bl2 = (const float*)d_in[19];
    float* out = (float*)d_out;

    float *dinvP, *dinvS, *Wc, *W2;
    __half *bufP0, *bufP1, *bufS0, *bufS1;
    int *rowP, *rowS, *curP, *curS, *bsum;
    int2 *srcwP, *srcwS;
    cudaGetSymbolAddress((void**)&bufP0, g_bufP0);
    cudaGetSymbolAddress((void**)&bufP1, g_bufP1);
    cudaGetSymbolAddress((void**)&bufS0, g_bufS0);
    cudaGetSymbolAddress((void**)&bufS1, g_bufS1);
    cudaGetSymbolAddress((void**)&dinvP, g_dinvP);
    cudaGetSymbolAddress((void**)&dinvS, g_dinvS);
    cudaGetSymbolAddress((void**)&rowP,  g_rowP);
    cudaGetSymbolAddress((void**)&rowS,  g_rowS);
    cudaGetSymbolAddress((void**)&curP,  g_curP);
    cudaGetSymbolAddress((void**)&curS,  g_curS);
    cudaGetSymbolAddress((void**)&srcwP, g_srcwP);
    cudaGetSymbolAddress((void**)&srcwS, g_srcwS);
    cudaGetSymbolAddress((void**)&Wc,    g_Wc);
    cudaGetSymbolAddress((void**)&W2,    g_W2);
    cudaGetSymbolAddress((void**)&bsum,  g_bsum);

    cudaFuncSetAttribute(k_prep, cudaFuncAttributeMaxDynamicSharedMemorySize, PREP_SMEM);

    if (g_s1 == nullptr) {
        cudaStreamCreateWithFlags(&g_s1, cudaStreamNonBlocking);
        cudaStreamCreateWithFlags(&g_s2, cudaStreamNonBlocking);
        cudaEventCreateWithFlags(&g_evRoot, cudaEventDisableTiming);
        cudaEventCreateWithFlags(&g_evCSR,  cudaEventDisableTiming);
        cudaEventCreateWithFlags(&g_evPrep, cudaEventDisableTiming);
        cudaEventCreateWithFlags(&g_evTail, cudaEventDisableTiming);
    }
    cudaStream_t s1 = g_s1, s2 = g_s2;

    const int EP = in_sizes[2] / 2;
    const int ES = in_sizes[3] / 2;
    const int EL = in_sizes[4];
    const int nbP = cdiv(NP, 1024), nbS = cdiv(NS, 1024);
    const int gP = cdiv(NP, BM), gS = cdiv(NS, BM);
    const int aggBlocks = cdiv((NP + NS) * 32, 256);

    float* W2cP = W2;
    float* b2cP = W2 + 64 * 64;
    float* W2cS = W2 + 64 * 64 + 64;
    float* b2cS = W2 + 2 * 64 * 64 + 64;

    // fork
    cudaEventRecord(g_evRoot, 0);
    cudaStreamWaitEvent(s1, g_evRoot, 0);
    cudaStreamWaitEvent(s2, g_evRoot, 0);

    // ---- s2: CSR build chain ----
    k_countB<<<cdiv(EP + ES, 256), 256, 0, s2>>>(ei_p, EP, ei_s, ES, curP, curS);
    k_scan1B<<<nbP + nbS, 1024, 0, s2>>>(curP, curS, rowP, rowS, bsum, nbP);
    k_scan2B<<<1, 1024, 0, s2>>>(bsum, nbP, nbS);
    k_scan3B<<<cdiv(NP + NS, 256), 256, 0, s2>>>(rowP, rowS, curP, curS, bsum, nbP, EP, ES, dinvP, dinvS);
    k_fillB<<<cdiv(EP + ES, 256), 256, 0, s2>>>(ei_p, EP, ei_s, ES, curP, curS,
                                                srcwP, srcwS, dinvP, dinvS);
    cudaEventRecord(g_evCSR, s2);
    k_reset<<<cdiv(NP, 256), 256, 0, s2>>>(curP, curS);
    cudaEventRecord(g_evTail, s2);

    // ---- s1: prep ----
    k_prep<<<1, 256, PREP_SMEM, s1>>>(Wproj, bproj, Wl1, bl1, Wp2, bp2, Ws2, bs2, Wc, W2);
    cudaEventRecord(g_evPrep, s1);

    // ---- s0 (main): merged P+S chain (all internal features fp16) ----
    k_gemm2<<<gP + gS, 256>>>(x_p, Wp1, bufP0, NP, PD, gP,
                              x_s, Ws1, bufS0, NS, SD);
    cudaStreamWaitEvent(0, g_evCSR, 0);
    k_aggregate2<<<aggBlocks, 256>>>(bufP0, bufP1, rowP, srcwP, dinvP, bp1,
                                     bufS0, bufS1, rowS, srcwS, dinvS, bs1);
    cudaStreamWaitEvent(0, g_evPrep, 0);
    k_gemm2h<<<gP + gS, 256>>>(bufP1, W2cP, bufP0, NP, gP,
                               bufS1, W2cS, bufS0, NS);
    k_aggregate2<<<aggBlocks, 256>>>(bufP0, bufP1, rowP, srcwP, dinvP, b2cP,
                                     bufS0, bufS1, rowS, srcwS, dinvS, b2cS);

    // ---- link prediction (fp16 features, 2 edges per warp) ----
    {
        long long threads = (long long)cdiv(EL, 2) * 32;
        int blocks = (int)((threads + 255) / 256);
        k_link<<<blocks, 256>>>(bufP1, bufS1, ed_p, ed_s, Wc + 128 * 64, Wl2, bl2, out, EL);
    }

    // join s2 tail (reset) back into the origin stream
    cudaStreamWaitEvent(0, g_evTail, 0);
}

// round 17
// speedup vs baseline: 1.0027x; 1.0027x over previous
#include <cuda_runtime.h>
#include <cuda_fp16.h>
#include <cstdint>
#include <cstdio>

// ---------------- problem constants ----------------
#define NP 100000
#define NS 50000
#define PD 1024
#define SD 512
#define HF 64
#define EPN 3200000
#define ESN 1600000
#define ELN 2000000

// ---------------- device scratch (static; zero-initialized at load) ----------------
// feature buffers hold fp16 rows (64 halfs = 128B)
__device__ float g_bufP0[(size_t)NP * HF / 2];
__device__ float g_bufP1[(size_t)NP * HF / 2];
__device__ float g_bufS0[(size_t)NS * HF / 2];
__device__ float g_bufS1[(size_t)NS * HF / 2];
__device__ float g_dinvP[NP];
__device__ float g_dinvS[NS];
__device__ int   g_rowP[NP + 1];
__device__ int   g_rowS[NS + 1];
__device__ int   g_curP[NP];   // counts -> cursor; zero at start of each replay
__device__ int   g_curS[NS];
__device__ int   g_srcP[EPN];
__device__ int   g_srcS[ESN];
__device__ float g_Wc[128 * 64 + 64];      // Wcomb [128,64] row-major, then bcomb[64]
__device__ float g_W2[2 * (64 * 64 + 64)]; // W2cP[64x64], b2cP[64], W2cS[64x64], b2cS[64]
__device__ int   g_bsum[256];

// ================= CSR build (both graphs in shared kernels) =================
__global__ void k_countB(const int* __restrict__ eiP, int EP,
                         const int* __restrict__ eiS, int ES,
                         int* __restrict__ cntP, int* __restrict__ cntS) {
    int e = blockIdx.x * blockDim.x + threadIdx.x;
    if (e < EP) {
        atomicAdd(&cntP[eiP[EP + e]], 1);
    } else if (e < EP + ES) {
        int l = e - EP;
        atomicAdd(&cntS[eiS[ES + l]], 1);
    }
}

__global__ void k_scan1B(const int* __restrict__ cntP, const int* __restrict__ cntS,
                         int* __restrict__ rowP, int* __restrict__ rowS,
                         int* __restrict__ blockSums, int nbP) {
    __shared__ int sh[1024];
    int b = blockIdx.x;
    const int* cnt;
    int* rowOut;
    int N, local0;
    if (b < nbP) { cnt = cntP; rowOut = rowP; N = NP; local0 = b * 1024; }
    else         { cnt = cntS; rowOut = rowS; N = NS; local0 = (b - nbP) * 1024; }
    int i = local0 + threadIdx.x;
    int v = (i < N) ? cnt[i] : 0;
    sh[threadIdx.x] = v;
    __syncthreads();
    for (int off = 1; off < 1024; off <<= 1) {
        int t = 0;
        if ((int)threadIdx.x >= off) t = sh[threadIdx.x - off];
        __syncthreads();
        sh[threadIdx.x] += t;
        __syncthreads();
    }
    int incl = sh[threadIdx.x];
    if (i < N) rowOut[i] = incl - v;
    if (threadIdx.x == 1023) blockSums[b] = incl;
}

__global__ void k_scan2B(int* __restrict__ blockSums, int nbP, int nbS) {
    __shared__ int sh[1024];
    int nb = nbP + nbS;
    int t = threadIdx.x;
    int v = (t < nb) ? blockSums[t] : 0;
    sh[t] = v;
    __syncthreads();
    for (int off = 1; off < 1024; off <<= 1) {
        int x = 0;
        if (t >= off) x = sh[t - off];
        __syncthreads();
        sh[t] += x;
        __syncthreads();
    }
    int excl = sh[t] - v;
    int sumP = sh[nbP - 1];
    if (t < nbP) blockSums[t] = excl;
    else if (t < nb) blockSums[t] = excl - sumP;
}

__global__ void k_scan3B(int* __restrict__ rowP, int* __restrict__ rowS,
                         int* __restrict__ curP, int* __restrict__ curS,
                         const int* __restrict__ blockSums, int nbP,
                         int EP, int ES,
                         float* __restrict__ dinvP, float* __restrict__ dinvS) {
    int i = blockIdx.x * blockDim.x + threadIdx.x;
    if (i < NP) {
        int r = rowP[i] + blockSums[i >> 10];
        int deg = curP[i];
        rowP[i] = r;
        curP[i] = r;
        dinvP[i] = rsqrtf((float)(deg + 1));
        if (i == 0) rowP[NP] = EP;
    } else if (i < NP + NS) {
        int l = i - NP;
        int r = rowS[l] + blockSums[(l >> 10) + nbP];
        int deg = curS[l];
        rowS[l] = r;
        curS[l] = r;
        dinvS[l] = rsqrtf((float)(deg + 1));
        if (l == 0) rowS[NS] = ES;
    }
}

__global__ void k_fillB(const int* __restrict__ eiP, int EP,
                        const int* __restrict__ eiS, int ES,
                        int* __restrict__ curP, int* __restrict__ curS,
                        int* __restrict__ srcP, int* __restrict__ srcS) {
    int e = blockIdx.x * blockDim.x + threadIdx.x;
    if (e < EP) {
        int d = eiP[EP + e];
        int p = atomicAdd(&curP[d], 1);
        srcP[p] = eiP[e];
    } else if (e < EP + ES) {
        int l = e - EP;
        int d = eiS[ES + l];
        int p = atomicAdd(&curS[d], 1);
        srcS[p] = eiS[l];
    }
}

__global__ void k_reset(int* __restrict__ curP, int* __restrict__ curS) {
    int i = blockIdx.x * blockDim.x + threadIdx.x;
    if (i < NP) curP[i] = 0;
    if (i < NS) curS[i] = 0;
}

// ======== tf32 tensor-core GEMM bodies (round-6 proven tiling) ========
#define BM 128
#define BN 64
#define BK 32
#define XPAD 40
#define WPAD 72

__device__ __forceinline__ unsigned f2tf32(float f) {
    unsigned u;
    asm("cvt.rna.tf32.f32 %0, %1;" : "=r"(u) : "f"(f));
    return u;
}

__device__ __forceinline__ void mma_tile(const unsigned* Xs, const unsigned* Ws,
                                         int rb, int cb, int lq, int lr,
                                         float acc[2][4][4]) {
#pragma unroll
    for (int ks = 0; ks < 4; ks++) {
        int k0 = ks * 8;
        unsigned a[2][4];
#pragma unroll
        for (int mt = 0; mt < 2; mt++) {
            int r = rb + mt * 16 + lq;
            a[mt][0] = Xs[r * XPAD + k0 + lr];
            a[mt][1] = Xs[(r + 8) * XPAD + k0 + lr];
            a[mt][2] = Xs[r * XPAD + k0 + 4 + lr];
            a[mt][3] = Xs[(r + 8) * XPAD + k0 + 4 + lr];
        }
        unsigned b[4][2];
#pragma unroll
        for (int nb = 0; nb < 4; nb++) {
            int c = cb + nb * 8 + lq;
            b[nb][0] = Ws[(k0 + lr) * WPAD + c];
            b[nb][1] = Ws[(k0 + 4 + lr) * WPAD + c];
        }
#pragma unroll
        for (int mt = 0; mt < 2; mt++)
#pragma unroll
            for (int nb = 0; nb < 4; nb++)
                asm volatile(
                    "mma.sync.aligned.m16n8k8.row.col.f32.tf32.tf32.f32 "
                    "{%0,%1,%2,%3}, {%4,%5,%6,%7}, {%8,%9}, {%0,%1,%2,%3};"
                    : "+f"(acc[mt][nb][0]), "+f"(acc[mt][nb][1]),
                      "+f"(acc[mt][nb][2]), "+f"(acc[mt][nb][3])
                    : "r"(a[mt][0]), "r"(a[mt][1]), "r"(a[mt][2]), "r"(a[mt][3]),
                      "r"(b[nb][0]), "r"(b[nb][1]));
    }
}

__device__ __forceinline__ void epilogue_h(__half* Y, int M, int row0, int rb, int cb,
                                           int lq, int lr, float acc[2][4][4]) {
#pragma unroll
    for (int mt = 0; mt < 2; mt++) {
#pragma unroll
        for (int nb = 0; nb < 4; nb++) {
            int r = row0 + rb + mt * 16 + lq;
            int c = cb + nb * 8 + 2 * lr;
            if (r < M)
                ((__half2*)Y)[(size_t)r * 32 + (c >> 1)] =
                    __floats2half2_rn(acc[mt][nb][0], acc[mt][nb][1]);
            if (r + 8 < M)
                ((__half2*)Y)[(size_t)(r + 8) * 32 + (c >> 1)] =
                    __floats2half2_rn(acc[mt][nb][2], acc[mt][nb][3]);
        }
    }
}

// fp32 X -> fp16 Y (layer 1)
__device__ __forceinline__ void gemm_body(const float* __restrict__ X,
                                          const float* __restrict__ W,
                                          __half* __restrict__ Y, int M, int K,
                                          int row0, unsigned* Xs, unsigned* Ws) {
    int tid = threadIdx.x;
    int wid = tid >> 5, lane = tid & 31;
    int lq = lane >> 2, lr = lane & 3;
    int rb = (wid & 3) * 32, cb = (wid >> 2) * 32;
    int nt = K / BK;

    int xr[4], xc[4];
#pragma unroll
    for (int l = 0; l < 4; l++) {
        int idx = tid + l * 256;
        xr[l] = idx >> 3;
        xc[l] = idx & 7;
    }
    int wk[2], wc[2];
#pragma unroll
    for (int l = 0; l < 2; l++) {
        int idx = tid + l * 256;
        wk[l] = idx >> 4;
        wc[l] = idx & 15;
    }

    float acc[2][4][4];
#pragma unroll
    for (int mt = 0; mt < 2; mt++)
#pragma unroll
        for (int nb = 0; nb < 4; nb++)
#pragma unroll
            for (int j = 0; j < 4; j++) acc[mt][nb][j] = 0.f;

    float4 xv[4], wv[2];
#pragma unroll
    for (int l = 0; l < 4; l++) {
        int gr = row0 + xr[l];
        xv[l] = (gr < M) ? *(const float4*)(X + (size_t)gr * K + xc[l] * 4)
                         : make_float4(0.f, 0.f, 0.f, 0.f);
    }
#pragma unroll
    for (int l = 0; l < 2; l++)
        wv[l] = *(const float4*)(W + (size_t)wk[l] * HF + wc[l] * 4);
#pragma unroll
    for (int l = 0; l < 4; l++) {
        uint4 u = make_uint4(f2tf32(xv[l].x), f2tf32(xv[l].y), f2tf32(xv[l].z), f2tf32(xv[l].w));
        *(uint4*)&Xs[xr[l] * XPAD + xc[l] * 4] = u;
    }
#pragma unroll
    for (int l = 0; l < 2; l++) {
        uint4 u = make_uint4(f2tf32(wv[l].x), f2tf32(wv[l].y), f2tf32(wv[l].z), f2tf32(wv[l].w));
        *(uint4*)&Ws[wk[l] * WPAD + wc[l] * 4] = u;
    }
    __syncthreads();

    for (int t = 0; t < nt; t++) {
        if (t + 1 < nt) {
            const float* Xn = X + (size_t)(t + 1) * BK;
            const float* Wn = W + (size_t)(t + 1) * BK * HF;
#pragma unroll
            for (int l = 0; l < 4; l++) {
                int gr = row0 + xr[l];
                xv[l] = (gr < M) ? *(const float4*)(Xn + (size_t)gr * K + xc[l] * 4)
                                 : make_float4(0.f, 0.f, 0.f, 0.f);
            }
#pragma unroll
            for (int l = 0; l < 2; l++)
                wv[l] = *(const float4*)(Wn + (size_t)wk[l] * HF + wc[l] * 4);
        }
        mma_tile(Xs, Ws, rb, cb, lq, lr, acc);
        __syncthreads();
        if (t + 1 < nt) {
#pragma unroll
            for (int l = 0; l < 4; l++) {
                uint4 u = make_uint4(f2tf32(xv[l].x), f2tf32(xv[l].y), f2tf32(xv[l].z), f2tf32(xv[l].w));
                *(uint4*)&Xs[xr[l] * XPAD + xc[l] * 4] = u;
            }
#pragma unroll
            for (int l = 0; l < 2; l++) {
                uint4 u = make_uint4(f2tf32(wv[l].x), f2tf32(wv[l].y), f2tf32(wv[l].z), f2tf32(wv[l].w));
                *(uint4*)&Ws[wk[l] * WPAD + wc[l] * 4] = u;
            }
            __syncthreads();
        }
    }
    epilogue_h(Y, M, row0, rb, cb, lq, lr, acc);
}

// fp16 X -> fp16 Y (layer 2, K=64)
__device__ __forceinline__ void gemm_body_h(const __half* __restrict__ X,
                                            const float* __restrict__ W,
                                            __half* __restrict__ Y, int M, int K,
                                            int row0, unsigned* Xs, unsigned* Ws) {
    int tid = threadIdx.x;
    int wid = tid >> 5, lane = tid & 31;
    int lq = lane >> 2, lr = lane & 3;
    int rb = (wid & 3) * 32, cb = (wid >> 2) * 32;
    int nt = K / BK;

    int xr[2], xc[2];
#pragma unroll
    for (int l = 0; l < 2; l++) {
        int idx = tid + l * 256;
        xr[l] = idx >> 2;
        xc[l] = idx & 3;
    }
    int wk[2], wc[2];
#pragma unroll
    for (int l = 0; l < 2; l++) {
        int idx = tid + l * 256;
        wk[l] = idx >> 4;
        wc[l] = idx & 15;
    }

    float acc[2][4][4];
#pragma unroll
    for (int mt = 0; mt < 2; mt++)
#pragma unroll
        for (int nb = 0; nb < 4; nb++)
#pragma unroll
            for (int j = 0; j < 4; j++) acc[mt][nb][j] = 0.f;

    for (int t = 0; t < nt; t++) {
#pragma unroll
        for (int l = 0; l < 2; l++) {
            int gr = row0 + xr[l];
            uint4 v = make_uint4(0u, 0u, 0u, 0u);
            if (gr < M)
                v = *(const uint4*)(X + (size_t)gr * K + t * BK + xc[l] * 8);
            const __half2* hp = (const __half2*)&v;
            unsigned o[8];
#pragma unroll
            for (int j = 0; j < 4; j++) {
                float2 f = __half22float2(hp[j]);
                o[2 * j] = f2tf32(f.x);
                o[2 * j + 1] = f2tf32(f.y);
            }
            *(uint4*)&Xs[xr[l] * XPAD + xc[l] * 8]     = make_uint4(o[0], o[1], o[2], o[3]);
            *(uint4*)&Xs[xr[l] * XPAD + xc[l] * 8 + 4] = make_uint4(o[4], o[5], o[6], o[7]);
        }
#pragma unroll
        for (int l = 0; l < 2; l++) {
            float4 w = *(const float4*)(W + (size_t)(t * BK + wk[l]) * HF + wc[l] * 4);
            uint4 u = make_uint4(f2tf32(w.x), f2tf32(w.y), f2tf32(w.z), f2tf32(w.w));
            *(uint4*)&Ws[wk[l] * WPAD + wc[l] * 4] = u;
        }
        __syncthreads();
        mma_tile(Xs, Ws, rb, cb, lq, lr, acc);
        __syncthreads();
    }
    epilogue_h(Y, M, row0, rb, cb, lq, lr, acc);
}

__global__ __launch_bounds__(256, 2) void k_gemm2(
    const float* __restrict__ X0, const float* __restrict__ W0, __half* __restrict__ Y0,
    int M0, int K0, int nb0,
    const float* __restrict__ X1, const float* __restrict__ W1, __half* __restrict__ Y1,
    int M1, int K1) {
    __shared__ unsigned Xs[BM * XPAD];
    __shared__ unsigned Ws[BK * WPAD];
    int b = blockIdx.x;
    if (b < nb0) gemm_body(X0, W0, Y0, M0, K0, b * BM, Xs, Ws);
    else         gemm_body(X1, W1, Y1, M1, K1, (b - nb0) * BM, Xs, Ws);
}

__global__ __launch_bounds__(256, 2) void k_gemm2h(
    const __half* __restrict__ X0, const float* __restrict__ W0, __half* __restrict__ Y0,
    int M0, int nb0,
    const __half* __restrict__ X1, const float* __restrict__ W1, __half* __restrict__ Y1,
    int M1) {
    __shared__ unsigned Xs[BM * XPAD];
    __shared__ unsigned Ws[BK * WPAD];
    int b = blockIdx.x;
    if (b < nb0) gemm_body_h(X0, W0, Y0, M0, HF, b * BM, Xs, Ws);
    else         gemm_body_h(X1, W1, Y1, M1, HF, (b - nb0) * BM, Xs, Ws);
}

// ---------------- merged GCN aggregation (fp16; one-wave grid-stride) ----------------
__device__ __forceinline__ void agg_node(const __half* __restrict__ H, __half* __restrict__ OUT,
                                         const int* __restrict__ row, const int* __restrict__ srcs,
                                         const float* __restrict__ dinv, const float* __restrict__ bias,
                                         int dst, int lane) {
    int half = lane >> 4;     // 0: even edges, 1: odd edges
    int hl = lane & 15;       // uint2 index within 128B row
    const uint2* Hp = (const uint2*)H;
    float4 a0 = make_float4(0.f, 0.f, 0.f, 0.f);
    float4 a1 = make_float4(0.f, 0.f, 0.f, 0.f);
    int s = row[dst], e = row[dst + 1];
    int i = s;
    for (; i + 4 <= e; i += 4) {
        int s0 = srcs[i + half];
        int s1 = srcs[i + 2 + half];
        float d0 = dinv[s0];
        float d1 = dinv[s1];
        uint2 u0 = Hp[(size_t)s0 * 16 + hl];
        uint2 u1 = Hp[(size_t)s1 * 16 + hl];
        float2 f00 = __half22float2(*(__half2*)&u0.x);
        float2 f01 = __half22float2(*(__half2*)&u0.y);
        float2 f10 = __half22float2(*(__half2*)&u1.x);
        float2 f11 = __half22float2(*(__half2*)&u1.y);
        a0.x += f00.x * d0; a0.y += f00.y * d0; a0.z += f01.x * d0; a0.w += f01.y * d0;
        a1.x += f10.x * d1; a1.y += f10.y * d1; a1.z += f11.x * d1; a1.w += f11.y * d1;
    }
    for (; i < e; i += 2) {
        int idx = i + half;
        if (idx < e) {
            int src = srcs[idx];
            float d = dinv[src];
            uint2 u = Hp[(size_t)src * 16 + hl];
            float2 f0 = __half22float2(*(__half2*)&u.x);
            float2 f1 = __half22float2(*(__half2*)&u.y);
            a0.x += f0.x * d; a0.y += f0.y * d; a0.z += f1.x * d; a0.w += f1.y * d;
        }
    }
    float4 acc = make_float4(a0.x + a1.x, a0.y + a1.y, a0.z + a1.z, a0.w + a1.w);
    acc.x += __shfl_down_sync(0xffffffffu, acc.x, 16);
    acc.y += __shfl_down_sync(0xffffffffu, acc.y, 16);
    acc.z += __shfl_down_sync(0xffffffffu, acc.z, 16);
    acc.w += __shfl_down_sync(0xffffffffu, acc.w, 16);
    if (half == 0) {
        float di = dinv[dst];
        uint2 us = Hp[(size_t)dst * 16 + hl];   // self-loop term
        float2 s0 = __half22float2(*(__half2*)&us.x);
        float2 s1 = __half22float2(*(__half2*)&us.y);
        float4 b4 = ((const float4*)bias)[hl];
        float4 o;
        o.x = (acc.x + s0.x * di) * di + b4.x;
        o.y = (acc.y + s0.y * di) * di + b4.y;
        o.z = (acc.z + s1.x * di) * di + b4.z;
        o.w = (acc.w + s1.y * di) * di + b4.w;
        __half2 p0 = __floats2half2_rn(o.x, o.y);
        __half2 p1 = __floats2half2_rn(o.z, o.w);
        uint2 u;
        u.x = *(unsigned*)&p0;
        u.y = *(unsigned*)&p1;
        ((uint2*)OUT)[(size_t)dst * 16 + hl] = u;
    }
}

// one-wave launch: every warp strides over nodes -> per-warp work ~= sum of ~16
// Poisson(32) degrees (sd ~4%), removing max-of-8 block imbalance + tail waves
__global__ void k_aggregate2(const __half* __restrict__ HP, __half* __restrict__ OP,
                             const int* __restrict__ rowP, const int* __restrict__ srcP,
                             const float* __restrict__ dinvP, const float* __restrict__ biasP,
                             const __half* __restrict__ HS, __half* __restrict__ OS,
                             const int* __restrict__ rowS, const int* __restrict__ srcS,
                             const float* __restrict__ dinvS, const float* __restrict__ biasS) {
    int gw = (blockIdx.x * blockDim.x + threadIdx.x) >> 5;
    int nw = (gridDim.x * blockDim.x) >> 5;
    int lane = threadIdx.x & 31;
    for (int n = gw; n < NP + NS; n += nw) {
        if (n < NP) agg_node(HP, OP, rowP, srcP, dinvP, biasP, n, lane);
        else        agg_node(HS, OS, rowS, srcS, dinvS, biasS, n - NP, lane);
    }
}

// ---- fused prep: Wc = Wproj@Wl1 (+bcomb), then W2cP/W2cS = Wp2/Ws2 @ Wc halves ----
__global__ void k_prep(const float* __restrict__ Wproj, const float* __restrict__ bproj,
                       const float* __restrict__ Wl1, const float* __restrict__ bl1,
                       const float* __restrict__ Wp2, const float* __restrict__ bp2,
                       const float* __restrict__ Ws2, const float* __restrict__ bs2,
                       float* __restrict__ Wc, float* __restrict__ W2) {
    extern __shared__ float sh[];
    float* sWl1 = sh;
    float* sWc  = sh + 128 * 64;
    for (int i = threadIdx.x; i < 128 * 64; i += blockDim.x) sWl1[i] = Wl1[i];
    __syncthreads();
    for (int o = threadIdx.x; o < 128 * 64; o += blockDim.x) {
        int i = o >> 6, j = o & 63;
        float s = 0.f;
        for (int k = 0; k < 128; k++) s += Wproj[i * 128 + k] * sWl1[k * 64 + j];
        sWc[o] = s;
        Wc[o] = s;
    }
    for (int j = threadIdx.x; j < 64; j += blockDim.x) {
        float s = bl1[j];
        for (int k = 0; k < 128; k++) s += bproj[k] * sWl1[k * 64 + j];
        Wc[128 * 64 + j] = s;
    }
    __syncthreads();
    float* W2cP = W2;
    float* b2cP = W2 + 64 * 64;
    float* W2cS = W2 + 64 * 64 + 64;
    float* b2cS = W2 + 2 * 64 * 64 + 64;
    for (int o = threadIdx.x; o < 64 * 64; o += blockDim.x) {
        int i = o >> 6, j = o & 63;
        float sp = 0.f, ss = 0.f;
        for (int k = 0; k < 64; k++) {
            sp += Wp2[i * 64 + k] * sWc[k * 64 + j];
            ss += Ws2[i * 64 + k] * sWc[(64 + k) * 64 + j];
        }
        W2cP[o] = sp;
        W2cS[o] = ss;
    }
    for (int j = threadIdx.x; j < 64; j += blockDim.x) {
        float sp = 0.f, ss = 0.f;
        for (int k = 0; k < 64; k++) {
            sp += bp2[k] * sWc[k * 64 + j];
            ss += bs2[k] * sWc[(64 + k) * 64 + j];
        }
        b2cP[j] = sp;
        b2cS[j] = ss;
    }
}
#define PREP_SMEM (2 * 128 * 64 * 4)   // 64 KB

// ---------------- link predictor: fp16 features, 2 edges per warp ----------------
__global__ void k_link(const __half* __restrict__ Ap, const __half* __restrict__ As,
                       const int* __restrict__ ep, const int* __restrict__ es,
                       const float* __restrict__ bc, const float* __restrict__ wl2,
                       const float* __restrict__ bl2, float* __restrict__ out, int EL) {
    int warp = (blockIdx.x * blockDim.x + threadIdx.x) >> 5;
    int lane = threadIdx.x & 31;
    int half = lane >> 4;
    int hl = lane & 15;
    int e = 2 * warp + half;
    if (e >= EL) return;
    int p = ep[e];
    int s = es[e];
    uint2 ua = ((const uint2*)Ap)[(size_t)p * 16 + hl];
    uint2 ub = ((const uint2*)As)[(size_t)s * 16 + hl];
    float2 a0 = __half22float2(*(__half2*)&ua.x);
    float2 a1 = __half22float2(*(__half2*)&ua.y);
    float2 b0 = __half22float2(*(__half2*)&ub.x);
    float2 b1 = __half22float2(*(__half2*)&ub.y);
    float4 c = ((const float4*)bc)[hl];
    float4 w = ((const float4*)wl2)[hl];
    float h0 = fmaxf(a0.x + b0.x + c.x, 0.f);
    float h1 = fmaxf(a0.y + b0.y + c.y, 0.f);
    float h2 = fmaxf(a1.x + b1.x + c.z, 0.f);
    float h3 = fmaxf(a1.y + b1.y + c.w, 0.f);
    float part = h0 * w.x + h1 * w.y + h2 * w.z + h3 * w.w;
#pragma unroll
    for (int off = 8; off; off >>= 1) part += __shfl_down_sync(0xffffffffu, part, off, 16);
    if (hl == 0) out[e] = part + bl2[0];
}

// ---------------- host orchestration ----------------
static inline int cdiv(int a, int b) { return (a + b - 1) / b; }

// streams/events created ONCE (pre-baseline on the correctness call) and reused.
static cudaStream_t g_s1 = nullptr, g_s2 = nullptr;
static cudaEvent_t g_evRoot, g_evCSR, g_evPrep, g_evTail;

extern "C" void kernel_launch(void* const* d_in, const int* in_sizes, int n_in,
                              void* d_out, int out_size) {
    const float* x_p  = (const float*)d_in[0];
    const float* x_s  = (const float*)d_in[1];
    const int*   ei_p = (const int*)d_in[2];
    const int*   ei_s = (const int*)d_in[3];
    const int*   ed_p = (const int*)d_in[4];
    const int*   ed_s = (const int*)d_in[5];
    const float* Wp1 = (const float*)d_in[6];
    const float* bp1 = (const float*)d_in[7];
    const float* Ws1 = (const float*)d_in[8];
    const float* bs1 = (const float*)d_in[9];
    const float* Wp2 = (const float*)d_in[10];
    const float* bp2 = (const float*)d_in[11];
    const float* Ws2 = (const float*)d_in[12];
    const float* bs2 = (const float*)d_in[13];
    const float* Wproj = (const float*)d_in[14];
    const float* bproj = (const float*)d_in[15];
    const float* Wl1 = (const float*)d_in[16];
    const float* bl1 = (const float*)d_in[17];
    const float* Wl2 = (const float*)d_in[18];
    const float* bl2 = (const float*)d_in[19];
    float* out = (float*)d_out;

    float *dinvP, *dinvS, *Wc, *W2;
    __half *bufP0, *bufP1, *bufS0, *bufS1;
    int *rowP, *rowS, *curP, *curS, *srcP, *srcS, *bsum;
    cudaGetSymbolAddress((void**)&bufP0, g_bufP0);
    cudaGetSymbolAddress((void**)&bufP1, g_bufP1);
    cudaGetSymbolAddress((void**)&bufS0, g_bufS0);
    cudaGetSymbolAddress((void**)&bufS1, g_bufS1);
    cudaGetSymbolAddress((void**)&dinvP, g_dinvP);
    cudaGetSymbolAddress((void**)&dinvS, g_dinvS);
    cudaGetSymbolAddress((void**)&rowP,  g_rowP);
    cudaGetSymbolAddress((void**)&rowS,  g_rowS);
    cudaGetSymbolAddress((void**)&curP,  g_curP);
    cudaGetSymbolAddress((void**)&curS,  g_curS);
    cudaGetSymbolAddress((void**)&srcP,  g_srcP);
    cudaGetSymbolAddress((void**)&srcS,  g_srcS);
    cudaGetSymbolAddress((void**)&Wc,    g_Wc);
    cudaGetSymbolAddress((void**)&W2,    g_W2);
    cudaGetSymbolAddress((void**)&bsum,  g_bsum);

    cudaFuncSetAttribute(k_prep, cudaFuncAttributeMaxDynamicSharedMemorySize, PREP_SMEM);

    if (g_s1 == nullptr) {
        cudaStreamCreateWithFlags(&g_s1, cudaStreamNonBlocking);
        cudaStreamCreateWithFlags(&g_s2, cudaStreamNonBlocking);
        cudaEventCreateWithFlags(&g_evRoot, cudaEventDisableTiming);
        cudaEventCreateWithFlags(&g_evCSR,  cudaEventDisableTiming);
        cudaEventCreateWithFlags(&g_evPrep, cudaEventDisableTiming);
        cudaEventCreateWithFlags(&g_evTail, cudaEventDisableTiming);
    }
    cudaStream_t s1 = g_s1, s2 = g_s2;

    const int EP = in_sizes[2] / 2;
    const int ES = in_sizes[3] / 2;
    const int EL = in_sizes[4];
    const int nbP = cdiv(NP, 1024), nbS = cdiv(NS, 1024);
    const int gP = cdiv(NP, BM), gS = cdiv(NS, BM);
    const int aggBlocks = 148 * 8;   // one resident wave (8 CTAs x 256 thr per SM)

    float* W2cP = W2;
    float* b2cP = W2 + 64 * 64;
    float* W2cS = W2 + 64 * 64 + 64;
    float* b2cS = W2 + 2 * 64 * 64 + 64;

    // fork
    cudaEventRecord(g_evRoot, 0);
    cudaStreamWaitEvent(s1, g_evRoot, 0);
    cudaStreamWaitEvent(s2, g_evRoot, 0);

    // ---- s2: CSR build chain ----
    k_countB<<<cdiv(EP + ES, 256), 256, 0, s2>>>(ei_p, EP, ei_s, ES, curP, curS);
    k_scan1B<<<nbP + nbS, 1024, 0, s2>>>(curP, curS, rowP, rowS, bsum, nbP);
    k_scan2B<<<1, 1024, 0, s2>>>(bsum, nbP, nbS);
    k_scan3B<<<cdiv(NP + NS, 256), 256, 0, s2>>>(rowP, rowS, curP, curS, bsum, nbP, EP, ES, dinvP, dinvS);
    k_fillB<<<cdiv(EP + ES, 256), 256, 0, s2>>>(ei_p, EP, ei_s, ES, curP, curS, srcP, srcS);
    cudaEventRecord(g_evCSR, s2);
    k_reset<<<cdiv(NP, 256), 256, 0, s2>>>(curP, curS);
    cudaEventRecord(g_evTail, s2);

    // ---- s1: prep ----
    k_prep<<<1, 256, PREP_SMEM, s1>>>(Wproj, bproj, Wl1, bl1, Wp2, bp2, Ws2, bs2, Wc, W2);
    cudaEventRecord(g_evPrep, s1);

    // ---- s0 (main): merged P+S chain (all internal features fp16) ----
    k_gemm2<<<gP + gS, 256>>>(x_p, Wp1, bufP0, NP, PD, gP,
                              x_s, Ws1, bufS0, NS, SD);
    cudaStreamWaitEvent(0, g_evCSR, 0);
    k_aggregate2<<<aggBlocks, 256>>>(bufP0, bufP1, rowP, srcP, dinvP, bp1,
                                     bufS0, bufS1, rowS, srcS, dinvS, bs1);
    cudaStreamWaitEvent(0, g_evPrep, 0);
    k_gemm2h<<<gP + gS, 256>>>(bufP1, W2cP, bufP0, NP, gP,
                               bufS1, W2cS, bufS0, NS);
    k_aggregate2<<<aggBlocks, 256>>>(bufP0, bufP1, rowP, srcP, dinvP, b2cP,
                                     bufS0, bufS1, rowS, srcS, dinvS, b2cS);

    // ---- link prediction (fp16 features, 2 edges per warp) ----
    {
        long long threads = (long long)cdiv(EL, 2) * 32;
        int blocks = (int)((threads + 255) / 256);
        k_link<<<blocks, 256>>>(bufP1, bufS1, ed_p, ed_s, Wc + 128 * 64, Wl2, bl2, out, EL);
    }

    // join s2 tail (reset) back into the origin stream
    cudaStreamWaitEvent(0, g_evTail, 0);
}